// round 8
// baseline (speedup 1.0000x reference)
#include <cuda_runtime.h>
#include <cstdint>
#include <math.h>

#define CC   256
#define K3   768
#define HWL  3136
#define WD   56
#define HALF_PI 1.5707963f
#define INV56   (1.0f / 56.0f)
#define RS768   0.03608439182435161f   // 1/sqrt(768)
#define NSPLIT  3

// Scratch (device globals — no allocations allowed). +128 pad for cp.async
// over-reads on the ragged last p-tile (stores are guarded).
__device__ uint32_t g_xtf [16 * CC * HWL + 128];     // tf32(x)
__device__ uint32_t g_w3tf[CC * K3];                 // tf32(W3)
__device__ uint32_t g_t1tf[16 * K3 * HWL + 128];     // tf32(unfold(x))
__device__ float    g_t3  [16 * CC * HWL];           // fp32 t3
__device__ uint32_t g_t6tf[16 * K3 * HWL + 128];     // tf32(max(t3, sin))
__device__ float    g_t7p [16 * NSPLIT * K3 * CC];   // split-K partials
__device__ uint32_t g_t7tf[16 * K3 * CC];            // tf32(t7)

static __device__ __forceinline__ uint32_t f2tf(float f) {
    uint32_t u; asm("cvt.rna.tf32.f32 %0, %1;" : "=r"(u) : "f"(f)); return u;
}
static __device__ __forceinline__ uint32_t cvta_s(const void* p) {
    uint32_t a;
    asm("{ .reg .u64 t; cvta.to.shared.u64 t, %1; cvt.u32.u64 %0, t; }" : "=r"(a) : "l"(p));
    return a;
}
static __device__ __forceinline__ void mma8(float d[4], const uint32_t* a, const uint32_t* b) {
    asm volatile(
        "mma.sync.aligned.m16n8k8.row.col.f32.tf32.tf32.f32 "
        "{%0,%1,%2,%3},{%4,%5,%6,%7},{%8,%9},{%0,%1,%2,%3};"
        : "+f"(d[0]), "+f"(d[1]), "+f"(d[2]), "+f"(d[3])
        : "r"(a[0]), "r"(a[1]), "r"(a[2]), "r"(a[3]), "r"(b[0]), "r"(b[1]));
}
#define CPA(dst, src) asm volatile("cp.async.cg.shared.global [%0], [%1], 16;" :: "r"(dst), "l"(src) : "memory")
#define CPC()         asm volatile("cp.async.commit_group;" ::: "memory")
#define CPW(N)        asm volatile("cp.async.wait_group %0;" :: "n"(N) : "memory")

// =====================================================================
// Precompute kernels
// =====================================================================
__global__ __launch_bounds__(256) void p_cvtx(const float4* __restrict__ x) {
    int i = blockIdx.x * 256 + threadIdx.x;
    float4 v = x[i];
    reinterpret_cast<uint4*>(g_xtf)[i] = make_uint4(f2tf(v.x), f2tf(v.y), f2tf(v.z), f2tf(v.w));
}
__global__ __launch_bounds__(256) void p_cvtw(const float4* __restrict__ w) {
    int i = blockIdx.x * 256 + threadIdx.x;
    float4 v = w[i];
    reinterpret_cast<uint4*>(g_w3tf)[i] = make_uint4(f2tf(v.x), f2tf(v.y), f2tf(v.z), f2tf(v.w));
}
__global__ __launch_bounds__(256) void p_t1(const float* __restrict__ x) {
    int idx = blockIdx.x * 256 + threadIdx.x;      // float4 index
    int p4 = idx % (HWL / 4);
    int r  = idx / (HWL / 4);
    int k  = r % K3, n = r / K3;
    int c = k / 3, tap = k - 3 * c, sh = 2 * tap - 2;
    int p = p4 * 4, w = p % WD;
    const float* xr = x + ((size_t)n * CC + c) * HWL + p + sh;
    float v[4];
#pragma unroll
    for (int j = 0; j < 4; j++)
        v[j] = ((unsigned)(w + j + sh) < WD) ? xr[j] : 0.f;
    reinterpret_cast<uint4*>(g_t1tf)[idx] =
        make_uint4(f2tf(v[0]), f2tf(v[1]), f2tf(v[2]), f2tf(v[3]));
}
__global__ __launch_bounds__(256) void p_t6(const float* __restrict__ x) {
    int idx = blockIdx.x * 256 + threadIdx.x;
    int p4 = idx % (HWL / 4);
    int r  = idx / (HWL / 4);
    int k  = r % K3, n = r / K3;
    int c = k / 3, tap = k - 3 * c, sh = 2 * tap - 2;
    int p = p4 * 4, w = p % WD;
    const float* xr = x + ((size_t)n * CC + c) * HWL + p + sh;
    float4 t3v = *reinterpret_cast<const float4*>(g_t3 + ((size_t)n * CC + c) * HWL + p);
    float tv[4] = {t3v.x, t3v.y, t3v.z, t3v.w};
    float v[4];
#pragma unroll
    for (int j = 0; j < 4; j++) {
        float s = ((unsigned)(w + j + sh) < WD) ? __sinf(HALF_PI * xr[j]) : 0.f;
        v[j] = fmaxf(tv[j], s);
    }
    reinterpret_cast<uint4*>(g_t6tf)[idx] =
        make_uint4(f2tf(v[0]), f2tf(v[1]), f2tf(v[2]), f2tf(v[3]));
}
__global__ __launch_bounds__(256) void k2r(const float4* __restrict__ p7w) {
    const int per_n = K3 * CC / 4;
    int idx = blockIdx.x * 256 + threadIdx.x;
    int n = idx / per_n, j = idx - n * per_n;
    const float4* base = reinterpret_cast<const float4*>(g_t7p) + (size_t)n * NSPLIT * per_n + j;
    float4 sv = base[0];
#pragma unroll
    for (int q = 1; q < NSPLIT; q++) {
        float4 v = base[(size_t)q * per_n];
        sv.x += v.x; sv.y += v.y; sv.z += v.z; sv.w += v.w;
    }
    float4 wv = p7w[j];
    reinterpret_cast<uint4*>(g_t7tf)[(size_t)n * per_n + j] =
        make_uint4(f2tf(sv.x * INV56 * wv.x), f2tf(sv.y * INV56 * wv.y),
                   f2tf(sv.z * INV56 * wv.z), f2tf(sv.w * INV56 * wv.w));
}

// =====================================================================
// GEMM common: 128x128 block tile, BK=16, 8 warps (2m x 4n), warp 64x32,
// 2-stage cp.async double buffer, 2 syncs / k-block, high occupancy.
// =====================================================================
#define ACC_INIT float acc[4][4][4]; \
    _Pragma("unroll") for (int i0 = 0; i0 < 4; i0++) \
    _Pragma("unroll") for (int j0 = 0; j0 < 4; j0++) \
    _Pragma("unroll") for (int r0 = 0; r0 < 4; r0++) acc[i0][j0][r0] = 0.f;

// ---------------- Stage 1: t3 = W3 @ t1 ----------------
// A: W3tf [m128][k16] pitch 20; B: t1tf [k16][p128] pitch 136
__global__ __launch_bounds__(256, 4) void k1() {
    __shared__ uint32_t As[2 * 2560];   // 128*20
    __shared__ uint32_t Bs[2 * 2176];   // 16*136
    const int t = threadIdx.x, lane = t & 31, warp = t >> 5;
    const int n = blockIdx.z, m0 = blockIdx.y * 128, p0 = blockIdx.x * 128;
    const int g = lane >> 2, c4 = lane & 3;
    const int wm = (warp & 1) * 64, wn = (warp >> 1) * 32;
    const uint32_t* t1n = g_t1tf + (size_t)n * K3 * HWL;

    const int rA = t >> 2, sA = t & 3;
    const uint32_t* srcA0 = g_w3tf + (size_t)(m0 + rA) * K3 + sA * 4;
    const uint32_t* srcA1 = g_w3tf + (size_t)(m0 + rA + 64) * K3 + sA * 4;
    const int rB0 = t >> 5, sB0 = t & 31;
    const uint32_t* srcB0 = t1n + (size_t)rB0 * HWL + p0 + sB0 * 4;
    const uint32_t* srcB1 = t1n + (size_t)(rB0 + 8) * HWL + p0 + sB0 * 4;
    const uint32_t dA0 = cvta_s(&As[rA * 20 + sA * 4]);
    const uint32_t dA1 = cvta_s(&As[(rA + 64) * 20 + sA * 4]);
    const uint32_t dB0 = cvta_s(&Bs[rB0 * 136 + sB0 * 4]);
    const uint32_t dB1 = cvta_s(&Bs[(rB0 + 8) * 136 + sB0 * 4]);

    auto load = [&](int kb, int buf) {
        int k0 = kb * 16;
        CPA(dA0 + buf * 10240, srcA0 + k0);
        CPA(dA1 + buf * 10240, srcA1 + k0);
        CPA(dB0 + buf * 8704,  srcB0 + (size_t)k0 * HWL);
        CPA(dB1 + buf * 8704,  srcB1 + (size_t)k0 * HWL);
    };

    ACC_INIT
    load(0, 0); CPC();
    const int NK = 48;
    for (int kb = 0; kb < NK; kb++) {
        int b = kb & 1;
        if (kb + 1 < NK) load(kb + 1, b ^ 1);
        CPC();
        CPW(1); __syncthreads();
        const uint32_t* Ab = As + b * 2560;
        const uint32_t* Bb = Bs + b * 2176;
#pragma unroll
        for (int th = 0; th < 2; th++) {
            int kc = th * 8 + c4;
            uint32_t af[4][4], bf[4][2];
#pragma unroll
            for (int mt = 0; mt < 4; mt++) {
                const uint32_t* ap = Ab + (wm + mt * 16 + g) * 20 + kc;
                af[mt][0] = ap[0]; af[mt][1] = ap[160]; af[mt][2] = ap[4]; af[mt][3] = ap[164];
            }
#pragma unroll
            for (int nt = 0; nt < 4; nt++) {
                const uint32_t* bp = Bb + kc * 136 + wn + nt * 8 + g;
                bf[nt][0] = bp[0]; bf[nt][1] = bp[544];
            }
#pragma unroll
            for (int mt = 0; mt < 4; mt++)
#pragma unroll
                for (int nt = 0; nt < 4; nt++) mma8(acc[mt][nt], af[mt], bf[nt]);
        }
        __syncthreads();
    }
    float* t3n = g_t3 + (size_t)n * CC * HWL;
#pragma unroll
    for (int mt = 0; mt < 4; mt++)
#pragma unroll
        for (int nt = 0; nt < 4; nt++) {
            int row = m0 + wm + mt * 16 + g;
            int col = p0 + wn + nt * 8 + c4 * 2;
            if (col < HWL) {
                *reinterpret_cast<float2*>(&t3n[(size_t)row * HWL + col]) =
                    make_float2(acc[mt][nt][0], acc[mt][nt][1]);
                *reinterpret_cast<float2*>(&t3n[(size_t)(row + 8) * HWL + col]) =
                    make_float2(acc[mt][nt][2], acc[mt][nt][3]);
            }
        }
}

// ---------------- Stage 2: t7p = t2 @ x^T (split-K=3, 1056/1056/1024) ----------------
// A: t2 rows (t1tf, k-3 wrap) [m128][p16] pitch 20; B: xtf [c'128][p16] pitch 20
__global__ __launch_bounds__(256, 4) void k2() {
    __shared__ uint32_t As[2 * 2560];   // 128*20
    __shared__ uint32_t Bs[2 * 2560];   // 128*20
    const int t = threadIdx.x, lane = t & 31, warp = t >> 5;
    const int zz = blockIdx.z, n = zz / NSPLIT, s = zz - n * NSPLIT;
    const int m0 = blockIdx.y * 128, c0 = blockIdx.x * 128;
    const int pbase = s * 1056;
    const int NK = (s == 2) ? 64 : 66;
    const int g = lane >> 2, c4 = lane & 3;
    const int wm = (warp & 1) * 64, wn = (warp >> 1) * 32;
    const uint32_t* t1n = g_t1tf + (size_t)n * K3 * HWL;
    const uint32_t* xn  = g_xtf  + (size_t)n * CC * HWL;

    const int rA = t >> 2, sA = t & 3;
    int mk0 = m0 + rA, mk1 = m0 + rA + 64;
    int sk0 = (mk0 >= 3) ? mk0 - 3 : mk0 + 765;
    int sk1 = (mk1 >= 3) ? mk1 - 3 : mk1 + 765;
    const uint32_t* srcA0 = t1n + (size_t)sk0 * HWL + pbase + sA * 4;
    const uint32_t* srcA1 = t1n + (size_t)sk1 * HWL + pbase + sA * 4;
    const uint32_t* srcB0 = xn + (size_t)(c0 + rA) * HWL + pbase + sA * 4;
    const uint32_t* srcB1 = xn + (size_t)(c0 + rA + 64) * HWL + pbase + sA * 4;
    const uint32_t dA0 = cvta_s(&As[rA * 20 + sA * 4]);
    const uint32_t dA1 = cvta_s(&As[(rA + 64) * 20 + sA * 4]);
    const uint32_t dB0 = cvta_s(&Bs[rA * 20 + sA * 4]);
    const uint32_t dB1 = cvta_s(&Bs[(rA + 64) * 20 + sA * 4]);

    auto load = [&](int kb, int buf) {
        int o = kb * 16;
        CPA(dA0 + buf * 10240, srcA0 + o);
        CPA(dA1 + buf * 10240, srcA1 + o);
        CPA(dB0 + buf * 10240, srcB0 + o);
        CPA(dB1 + buf * 10240, srcB1 + o);
    };

    ACC_INIT
    load(0, 0); CPC();
    for (int kb = 0; kb < NK; kb++) {
        int b = kb & 1;
        if (kb + 1 < NK) load(kb + 1, b ^ 1);
        CPC();
        CPW(1); __syncthreads();
        const uint32_t* Ab = As + b * 2560;
        const uint32_t* Bb = Bs + b * 2560;
#pragma unroll
        for (int th = 0; th < 2; th++) {
            int kc = th * 8 + c4;
            uint32_t af[4][4], bf[4][2];
#pragma unroll
            for (int mt = 0; mt < 4; mt++) {
                const uint32_t* ap = Ab + (wm + mt * 16 + g) * 20 + kc;
                af[mt][0] = ap[0]; af[mt][1] = ap[160]; af[mt][2] = ap[4]; af[mt][3] = ap[164];
            }
#pragma unroll
            for (int nt = 0; nt < 4; nt++) {
                const uint32_t* bp = Bb + (wn + nt * 8 + g) * 20 + kc;
                bf[nt][0] = bp[0]; bf[nt][1] = bp[4];
            }
#pragma unroll
            for (int mt = 0; mt < 4; mt++)
#pragma unroll
                for (int nt = 0; nt < 4; nt++) mma8(acc[mt][nt], af[mt], bf[nt]);
        }
        __syncthreads();
    }
    float* dst = g_t7p + (size_t)(n * NSPLIT + s) * K3 * CC;
#pragma unroll
    for (int mt = 0; mt < 4; mt++)
#pragma unroll
        for (int nt = 0; nt < 4; nt++) {
            int row = m0 + wm + mt * 16 + g;
            int col = c0 + wn + nt * 8 + c4 * 2;
            *reinterpret_cast<float2*>(&dst[(size_t)row * CC + col]) =
                make_float2(acc[mt][nt][0], acc[mt][nt][1]);
            *reinterpret_cast<float2*>(&dst[(size_t)(row + 8) * CC + col]) =
                make_float2(acc[mt][nt][2], acc[mt][nt][3]);
        }
}

// ---------------- Stage 3: out = (t6^T @ t7) / sqrt(768) ----------------
// A: t7tf [k16][c'128] pitch 136; B: t6tf [k16][p128] pitch 136
__global__ __launch_bounds__(256, 4) void k3(float* __restrict__ out) {
    __shared__ uint32_t As[2 * 2176];   // 16*136
    __shared__ uint32_t Bs[2 * 2176];   // 16*136
    const int t = threadIdx.x, lane = t & 31, warp = t >> 5;
    const int n = blockIdx.z, m0 = blockIdx.y * 128, p0 = blockIdx.x * 128;
    const int g = lane >> 2, c4 = lane & 3;
    const int wm = (warp & 1) * 64, wn = (warp >> 1) * 32;
    const uint32_t* t7n = g_t7tf + (size_t)n * K3 * CC;
    const uint32_t* t6n = g_t6tf + (size_t)n * K3 * HWL;

    const int r0 = t >> 5, s0 = t & 31;
    const uint32_t* srcA0 = t7n + (size_t)r0 * CC + m0 + s0 * 4;
    const uint32_t* srcA1 = t7n + (size_t)(r0 + 8) * CC + m0 + s0 * 4;
    const uint32_t* srcB0 = t6n + (size_t)r0 * HWL + p0 + s0 * 4;
    const uint32_t* srcB1 = t6n + (size_t)(r0 + 8) * HWL + p0 + s0 * 4;
    const uint32_t dA0 = cvta_s(&As[r0 * 136 + s0 * 4]);
    const uint32_t dA1 = cvta_s(&As[(r0 + 8) * 136 + s0 * 4]);
    const uint32_t dB0 = cvta_s(&Bs[r0 * 136 + s0 * 4]);
    const uint32_t dB1 = cvta_s(&Bs[(r0 + 8) * 136 + s0 * 4]);

    auto load = [&](int kb, int buf) {
        int k0 = kb * 16;
        CPA(dA0 + buf * 8704, srcA0 + (size_t)k0 * CC);
        CPA(dA1 + buf * 8704, srcA1 + (size_t)k0 * CC);
        CPA(dB0 + buf * 8704, srcB0 + (size_t)k0 * HWL);
        CPA(dB1 + buf * 8704, srcB1 + (size_t)k0 * HWL);
    };

    ACC_INIT
    load(0, 0); CPC();
    const int NK = 48;
    for (int kb = 0; kb < NK; kb++) {
        int b = kb & 1;
        if (kb + 1 < NK) load(kb + 1, b ^ 1);
        CPC();
        CPW(1); __syncthreads();
        const uint32_t* Ab = As + b * 2176;
        const uint32_t* Bb = Bs + b * 2176;
#pragma unroll
        for (int th = 0; th < 2; th++) {
            int kc = th * 8 + c4;
            uint32_t af[4][4], bf[4][2];
#pragma unroll
            for (int mt = 0; mt < 4; mt++) {
                const uint32_t* ap = Ab + kc * 136 + wm + mt * 16 + g;
                af[mt][0] = ap[0]; af[mt][1] = ap[8]; af[mt][2] = ap[544]; af[mt][3] = ap[552];
            }
#pragma unroll
            for (int nt = 0; nt < 4; nt++) {
                const uint32_t* bp = Bb + kc * 136 + wn + nt * 8 + g;
                bf[nt][0] = bp[0]; bf[nt][1] = bp[544];
            }
#pragma unroll
            for (int mt = 0; mt < 4; mt++)
#pragma unroll
                for (int nt = 0; nt < 4; nt++) mma8(acc[mt][nt], af[mt], bf[nt]);
        }
        __syncthreads();
    }
#pragma unroll
    for (int mt = 0; mt < 4; mt++)
#pragma unroll
        for (int nt = 0; nt < 4; nt++) {
            int row = m0 + wm + mt * 16 + g;
            int col = p0 + wn + nt * 8 + c4 * 2;
            if (col < HWL) {
                float* o0 = out + ((size_t)n * CC + row) * HWL + col;
                float* o1 = out + ((size_t)n * CC + row + 8) * HWL + col;
                *reinterpret_cast<float2*>(o0) =
                    make_float2(acc[mt][nt][0] * RS768, acc[mt][nt][1] * RS768);
                *reinterpret_cast<float2*>(o1) =
                    make_float2(acc[mt][nt][2] * RS768, acc[mt][nt][3] * RS768);
            }
        }
}

extern "C" void kernel_launch(void* const* d_in, const int* in_sizes, int n_in,
                              void* d_out, int out_size) {
    const float* x   = (const float*)d_in[0];   // (16, 256, 56, 56)
    const float* W3  = (const float*)d_in[1];   // (256, 768)
    const float* p7w = (const float*)d_in[2];   // (1, 256, 3, 256)
    float* out = (float*)d_out;                 // (16, 256, 56, 56)

    // Max shared-memory carveout so 4-5 CTAs/SM fit (idempotent attr sets).
    cudaFuncSetAttribute(k1, cudaFuncAttributePreferredSharedMemoryCarveout, 100);
    cudaFuncSetAttribute(k2, cudaFuncAttributePreferredSharedMemoryCarveout, 100);
    cudaFuncSetAttribute(k3, cudaFuncAttributePreferredSharedMemoryCarveout, 100);

    p_cvtx<<<12544, 256>>>((const float4*)x);
    p_cvtw<<<192, 256>>>((const float4*)W3);
    p_t1  <<<37632, 256>>>(x);
    k2    <<<dim3(2, 6, 48), 256>>>();
    k1    <<<dim3(25, 2, 16), 256>>>();
    p_t6  <<<37632, 256>>>(x);
    k2r   <<<3072, 256>>>((const float4*)p7w);
    k3    <<<dim3(25, 2, 16), 256>>>(out);
}

// round 9
// speedup vs baseline: 3.2751x; 3.2751x over previous
#include <cuda_runtime.h>
#include <cstdint>
#include <math.h>

#define CC   256
#define K3   768
#define HWL  3136
#define WD   56
#define HALF_PI 1.5707963f
#define INV56   (1.0f / 56.0f)
#define RS768   0.03608439182435161f   // 1/sqrt(768)
#define NSPLIT  3

// Scratch (device globals — no allocations allowed). +128 pad for cp.async
// over-reads on the ragged last p-tile (stores are guarded).
__device__ uint32_t g_w3tf[CC * K3];                 // tf32(W3)
__device__ uint32_t g_t1tf[16 * K3 * HWL + 128];     // tf32(unfold(x)); rows 3c+1 == tf32(x[c])
__device__ float    g_t3  [16 * CC * HWL];           // fp32 t3
__device__ uint32_t g_t6tf[16 * K3 * HWL + 128];     // tf32(max(t3, sin))
__device__ float    g_t7p [16 * NSPLIT * K3 * CC];   // split-K partials
__device__ uint32_t g_t7tf[16 * K3 * CC];            // tf32(t7)

static __device__ __forceinline__ uint32_t f2tf(float f) {
    uint32_t u; asm("cvt.rna.tf32.f32 %0, %1;" : "=r"(u) : "f"(f)); return u;
}
static __device__ __forceinline__ uint32_t cvta_s(const void* p) {
    uint32_t a;
    asm("{ .reg .u64 t; cvta.to.shared.u64 t, %1; cvt.u32.u64 %0, t; }" : "=r"(a) : "l"(p));
    return a;
}
static __device__ __forceinline__ void mma8(float d[4], const uint32_t* a, const uint32_t* b) {
    asm volatile(
        "mma.sync.aligned.m16n8k8.row.col.f32.tf32.tf32.f32 "
        "{%0,%1,%2,%3},{%4,%5,%6,%7},{%8,%9},{%0,%1,%2,%3};"
        : "+f"(d[0]), "+f"(d[1]), "+f"(d[2]), "+f"(d[3])
        : "r"(a[0]), "r"(a[1]), "r"(a[2]), "r"(a[3]), "r"(b[0]), "r"(b[1]));
}
#define CPA(dst, src) asm volatile("cp.async.cg.shared.global [%0], [%1], 16;" :: "r"(dst), "l"(src) : "memory")
#define CPC()         asm volatile("cp.async.commit_group;" ::: "memory")
#define CPW(N)        asm volatile("cp.async.wait_group %0;" :: "n"(N) : "memory")

// =====================================================================
// Precompute kernels
// =====================================================================
__global__ __launch_bounds__(256) void p_cvtw(const float4* __restrict__ w) {
    int i = blockIdx.x * 256 + threadIdx.x;
    float4 v = w[i];
    reinterpret_cast<uint4*>(g_w3tf)[i] = make_uint4(f2tf(v.x), f2tf(v.y), f2tf(v.z), f2tf(v.w));
}
__global__ __launch_bounds__(256) void p_t1(const float* __restrict__ x) {
    int idx = blockIdx.x * 256 + threadIdx.x;      // float4 index
    int p4 = idx % (HWL / 4);
    int r  = idx / (HWL / 4);
    int k  = r % K3, n = r / K3;
    int c = k / 3, tap = k - 3 * c, sh = 2 * tap - 2;
    int p = p4 * 4, w = p % WD;
    const float* xr = x + ((size_t)n * CC + c) * HWL + p + sh;
    float v[4];
#pragma unroll
    for (int j = 0; j < 4; j++)
        v[j] = ((unsigned)(w + j + sh) < WD) ? xr[j] : 0.f;
    reinterpret_cast<uint4*>(g_t1tf)[idx] =
        make_uint4(f2tf(v[0]), f2tf(v[1]), f2tf(v[2]), f2tf(v[3]));
}
__global__ __launch_bounds__(256) void p_t6(const float* __restrict__ x) {
    int idx = blockIdx.x * 256 + threadIdx.x;
    int p4 = idx % (HWL / 4);
    int r  = idx / (HWL / 4);
    int k  = r % K3, n = r / K3;
    int c = k / 3, tap = k - 3 * c, sh = 2 * tap - 2;
    int p = p4 * 4, w = p % WD;
    const float* xr = x + ((size_t)n * CC + c) * HWL + p + sh;
    float4 t3v = *reinterpret_cast<const float4*>(g_t3 + ((size_t)n * CC + c) * HWL + p);
    float tv[4] = {t3v.x, t3v.y, t3v.z, t3v.w};
    float v[4];
#pragma unroll
    for (int j = 0; j < 4; j++) {
        float s = ((unsigned)(w + j + sh) < WD) ? __sinf(HALF_PI * xr[j]) : 0.f;
        v[j] = fmaxf(tv[j], s);
    }
    reinterpret_cast<uint4*>(g_t6tf)[idx] =
        make_uint4(f2tf(v[0]), f2tf(v[1]), f2tf(v[2]), f2tf(v[3]));
}
__global__ __launch_bounds__(256) void k2r(const float4* __restrict__ p7w) {
    const int per_n = K3 * CC / 4;
    int idx = blockIdx.x * 256 + threadIdx.x;
    int n = idx / per_n, j = idx - n * per_n;
    const float4* base = reinterpret_cast<const float4*>(g_t7p) + (size_t)n * NSPLIT * per_n + j;
    float4 sv = base[0];
#pragma unroll
    for (int q = 1; q < NSPLIT; q++) {
        float4 v = base[(size_t)q * per_n];
        sv.x += v.x; sv.y += v.y; sv.z += v.z; sv.w += v.w;
    }
    float4 wv = p7w[j];
    reinterpret_cast<uint4*>(g_t7tf)[(size_t)n * per_n + j] =
        make_uint4(f2tf(sv.x * INV56 * wv.x), f2tf(sv.y * INV56 * wv.y),
                   f2tf(sv.z * INV56 * wv.z), f2tf(sv.w * INV56 * wv.w));
}

// =====================================================================
// GEMM common: 128x128 block tile, BK=16, 8 warps (2m x 4n), warp 64x32,
// 3-stage cp.async pipeline, 1 sync / k-block.
// =====================================================================
#define ACC_INIT float acc[4][4][4]; \
    _Pragma("unroll") for (int i0 = 0; i0 < 4; i0++) \
    _Pragma("unroll") for (int j0 = 0; j0 < 4; j0++) \
    _Pragma("unroll") for (int r0 = 0; r0 < 4; r0++) acc[i0][j0][r0] = 0.f;

// ---------------- Stage 1: t3 = W3 @ t1 ----------------
// A: W3tf [m128][k16] pitch 20; B: t1tf [k16][p128] pitch 136
__global__ __launch_bounds__(256, 2) void k1() {
    __shared__ uint32_t As[3 * 2560];   // 128*20
    __shared__ uint32_t Bs[3 * 2176];   // 16*136
    const int t = threadIdx.x, lane = t & 31, warp = t >> 5;
    const int n = blockIdx.z, m0 = blockIdx.y * 128, p0 = blockIdx.x * 128;
    const int g = lane >> 2, c4 = lane & 3;
    const int wm = (warp & 1) * 64, wn = (warp >> 1) * 32;
    const uint32_t* t1n = g_t1tf + (size_t)n * K3 * HWL;

    const int rA = t >> 2, sA = t & 3;
    const uint32_t* srcA0 = g_w3tf + (size_t)(m0 + rA) * K3 + sA * 4;
    const uint32_t* srcA1 = g_w3tf + (size_t)(m0 + rA + 64) * K3 + sA * 4;
    const int rB0 = t >> 5, sB0 = t & 31;
    const uint32_t* srcB0 = t1n + (size_t)rB0 * HWL + p0 + sB0 * 4;
    const uint32_t* srcB1 = t1n + (size_t)(rB0 + 8) * HWL + p0 + sB0 * 4;
    const uint32_t dA0 = cvta_s(&As[rA * 20 + sA * 4]);
    const uint32_t dA1 = cvta_s(&As[(rA + 64) * 20 + sA * 4]);
    const uint32_t dB0 = cvta_s(&Bs[rB0 * 136 + sB0 * 4]);
    const uint32_t dB1 = cvta_s(&Bs[(rB0 + 8) * 136 + sB0 * 4]);

    auto load = [&](int kb, int buf) {
        int k0 = kb * 16;
        CPA(dA0 + buf * 10240, srcA0 + k0);
        CPA(dA1 + buf * 10240, srcA1 + k0);
        CPA(dB0 + buf * 8704,  srcB0 + (size_t)k0 * HWL);
        CPA(dB1 + buf * 8704,  srcB1 + (size_t)k0 * HWL);
    };

    ACC_INIT
    load(0, 0); CPC(); load(1, 1); CPC();
    const int NK = 48;
    for (int kb = 0; kb < NK; kb++) {
        int b = kb % 3;
        CPW(1); __syncthreads();
        if (kb + 2 < NK) load(kb + 2, (kb + 2) % 3);
        CPC();
        const uint32_t* Ab = As + b * 2560;
        const uint32_t* Bb = Bs + b * 2176;
#pragma unroll
        for (int th = 0; th < 2; th++) {
            int kc = th * 8 + c4;
            uint32_t af[4][4], bf[4][2];
#pragma unroll
            for (int mt = 0; mt < 4; mt++) {
                const uint32_t* ap = Ab + (wm + mt * 16 + g) * 20 + kc;
                af[mt][0] = ap[0]; af[mt][1] = ap[160]; af[mt][2] = ap[4]; af[mt][3] = ap[164];
            }
#pragma unroll
            for (int nt = 0; nt < 4; nt++) {
                const uint32_t* bp = Bb + kc * 136 + wn + nt * 8 + g;
                bf[nt][0] = bp[0]; bf[nt][1] = bp[544];
            }
#pragma unroll
            for (int mt = 0; mt < 4; mt++)
#pragma unroll
                for (int nt = 0; nt < 4; nt++) mma8(acc[mt][nt], af[mt], bf[nt]);
        }
    }
    float* t3n = g_t3 + (size_t)n * CC * HWL;
#pragma unroll
    for (int mt = 0; mt < 4; mt++)
#pragma unroll
        for (int nt = 0; nt < 4; nt++) {
            int row = m0 + wm + mt * 16 + g;
            int col = p0 + wn + nt * 8 + c4 * 2;
            if (col < HWL) {
                *reinterpret_cast<float2*>(&t3n[(size_t)row * HWL + col]) =
                    make_float2(acc[mt][nt][0], acc[mt][nt][1]);
                *reinterpret_cast<float2*>(&t3n[(size_t)(row + 8) * HWL + col]) =
                    make_float2(acc[mt][nt][2], acc[mt][nt][3]);
            }
        }
}

// ---------------- Stage 2: t7p = t2 @ x^T (split-K=3: 1056/1056/1024) ----------------
// A: t2 rows (t1tf, k-3 wrap) [m128][p16] pitch 20
// B: x rows = t1tf rows 3c'+1 [c'128][p16] pitch 20
__global__ __launch_bounds__(256, 2) void k2() {
    __shared__ uint32_t As[3 * 2560];   // 128*20
    __shared__ uint32_t Bs[3 * 2560];   // 128*20
    const int t = threadIdx.x, lane = t & 31, warp = t >> 5;
    const int zz = blockIdx.z, n = zz / NSPLIT, s = zz - n * NSPLIT;
    const int m0 = blockIdx.y * 128, c0 = blockIdx.x * 128;
    const int pbase = s * 1056;
    const int NK = (s == 2) ? 64 : 66;
    const int g = lane >> 2, c4 = lane & 3;
    const int wm = (warp & 1) * 64, wn = (warp >> 1) * 32;
    const uint32_t* t1n = g_t1tf + (size_t)n * K3 * HWL;

    const int rA = t >> 2, sA = t & 3;
    int mk0 = m0 + rA, mk1 = m0 + rA + 64;
    int sk0 = (mk0 >= 3) ? mk0 - 3 : mk0 + 765;
    int sk1 = (mk1 >= 3) ? mk1 - 3 : mk1 + 765;
    const uint32_t* srcA0 = t1n + (size_t)sk0 * HWL + pbase + sA * 4;
    const uint32_t* srcA1 = t1n + (size_t)sk1 * HWL + pbase + sA * 4;
    const uint32_t* srcB0 = t1n + (size_t)(3 * (c0 + rA) + 1) * HWL + pbase + sA * 4;
    const uint32_t* srcB1 = t1n + (size_t)(3 * (c0 + rA + 64) + 1) * HWL + pbase + sA * 4;
    const uint32_t dA0 = cvta_s(&As[rA * 20 + sA * 4]);
    const uint32_t dA1 = cvta_s(&As[(rA + 64) * 20 + sA * 4]);
    const uint32_t dB0 = cvta_s(&Bs[rA * 20 + sA * 4]);
    const uint32_t dB1 = cvta_s(&Bs[(rA + 64) * 20 + sA * 4]);

    auto load = [&](int kb, int buf) {
        int o = kb * 16;
        CPA(dA0 + buf * 10240, srcA0 + o);
        CPA(dA1 + buf * 10240, srcA1 + o);
        CPA(dB0 + buf * 10240, srcB0 + o);
        CPA(dB1 + buf * 10240, srcB1 + o);
    };

    ACC_INIT
    load(0, 0); CPC(); load(1, 1); CPC();
    for (int kb = 0; kb < NK; kb++) {
        int b = kb % 3;
        CPW(1); __syncthreads();
        if (kb + 2 < NK) load(kb + 2, (kb + 2) % 3);
        CPC();
        const uint32_t* Ab = As + b * 2560;
        const uint32_t* Bb = Bs + b * 2560;
#pragma unroll
        for (int th = 0; th < 2; th++) {
            int kc = th * 8 + c4;
            uint32_t af[4][4], bf[4][2];
#pragma unroll
            for (int mt = 0; mt < 4; mt++) {
                const uint32_t* ap = Ab + (wm + mt * 16 + g) * 20 + kc;
                af[mt][0] = ap[0]; af[mt][1] = ap[160]; af[mt][2] = ap[4]; af[mt][3] = ap[164];
            }
#pragma unroll
            for (int nt = 0; nt < 4; nt++) {
                const uint32_t* bp = Bb + (wn + nt * 8 + g) * 20 + kc;
                bf[nt][0] = bp[0]; bf[nt][1] = bp[4];
            }
#pragma unroll
            for (int mt = 0; mt < 4; mt++)
#pragma unroll
                for (int nt = 0; nt < 4; nt++) mma8(acc[mt][nt], af[mt], bf[nt]);
        }
    }
    float* dst = g_t7p + (size_t)(n * NSPLIT + s) * K3 * CC;
#pragma unroll
    for (int mt = 0; mt < 4; mt++)
#pragma unroll
        for (int nt = 0; nt < 4; nt++) {
            int row = m0 + wm + mt * 16 + g;
            int col = c0 + wn + nt * 8 + c4 * 2;
            *reinterpret_cast<float2*>(&dst[(size_t)row * CC + col]) =
                make_float2(acc[mt][nt][0], acc[mt][nt][1]);
            *reinterpret_cast<float2*>(&dst[(size_t)(row + 8) * CC + col]) =
                make_float2(acc[mt][nt][2], acc[mt][nt][3]);
        }
}

// ---------------- Stage 3: out = (t6^T @ t7) / sqrt(768) ----------------
// A: t7tf [k16][c'128] pitch 136; B: t6tf [k16][p128] pitch 136
__global__ __launch_bounds__(256, 2) void k3(float* __restrict__ out) {
    __shared__ uint32_t As[3 * 2176];   // 16*136
    __shared__ uint32_t Bs[3 * 2176];   // 16*136
    const int t = threadIdx.x, lane = t & 31, warp = t >> 5;
    const int n = blockIdx.z, m0 = blockIdx.y * 128, p0 = blockIdx.x * 128;
    const int g = lane >> 2, c4 = lane & 3;
    const int wm = (warp & 1) * 64, wn = (warp >> 1) * 32;
    const uint32_t* t7n = g_t7tf + (size_t)n * K3 * CC;
    const uint32_t* t6n = g_t6tf + (size_t)n * K3 * HWL;

    const int r0 = t >> 5, s0 = t & 31;
    const uint32_t* srcA0 = t7n + (size_t)r0 * CC + m0 + s0 * 4;
    const uint32_t* srcA1 = t7n + (size_t)(r0 + 8) * CC + m0 + s0 * 4;
    const uint32_t* srcB0 = t6n + (size_t)r0 * HWL + p0 + s0 * 4;
    const uint32_t* srcB1 = t6n + (size_t)(r0 + 8) * HWL + p0 + s0 * 4;
    const uint32_t dA0 = cvta_s(&As[r0 * 136 + s0 * 4]);
    const uint32_t dA1 = cvta_s(&As[(r0 + 8) * 136 + s0 * 4]);
    const uint32_t dB0 = cvta_s(&Bs[r0 * 136 + s0 * 4]);
    const uint32_t dB1 = cvta_s(&Bs[(r0 + 8) * 136 + s0 * 4]);

    auto load = [&](int kb, int buf) {
        int k0 = kb * 16;
        CPA(dA0 + buf * 8704, srcA0 + (size_t)k0 * CC);
        CPA(dA1 + buf * 8704, srcA1 + (size_t)k0 * CC);
        CPA(dB0 + buf * 8704, srcB0 + (size_t)k0 * HWL);
        CPA(dB1 + buf * 8704, srcB1 + (size_t)k0 * HWL);
    };

    ACC_INIT
    load(0, 0); CPC(); load(1, 1); CPC();
    const int NK = 48;
    for (int kb = 0; kb < NK; kb++) {
        int b = kb % 3;
        CPW(1); __syncthreads();
        if (kb + 2 < NK) load(kb + 2, (kb + 2) % 3);
        CPC();
        const uint32_t* Ab = As + b * 2176;
        const uint32_t* Bb = Bs + b * 2176;
#pragma unroll
        for (int th = 0; th < 2; th++) {
            int kc = th * 8 + c4;
            uint32_t af[4][4], bf[4][2];
#pragma unroll
            for (int mt = 0; mt < 4; mt++) {
                const uint32_t* ap = Ab + kc * 136 + wm + mt * 16 + g;
                af[mt][0] = ap[0]; af[mt][1] = ap[8]; af[mt][2] = ap[544]; af[mt][3] = ap[552];
            }
#pragma unroll
            for (int nt = 0; nt < 4; nt++) {
                const uint32_t* bp = Bb + kc * 136 + wn + nt * 8 + g;
                bf[nt][0] = bp[0]; bf[nt][1] = bp[544];
            }
#pragma unroll
            for (int mt = 0; mt < 4; mt++)
#pragma unroll
                for (int nt = 0; nt < 4; nt++) mma8(acc[mt][nt], af[mt], bf[nt]);
        }
    }
#pragma unroll
    for (int mt = 0; mt < 4; mt++)
#pragma unroll
        for (int nt = 0; nt < 4; nt++) {
            int row = m0 + wm + mt * 16 + g;
            int col = p0 + wn + nt * 8 + c4 * 2;
            if (col < HWL) {
                float* o0 = out + ((size_t)n * CC + row) * HWL + col;
                float* o1 = out + ((size_t)n * CC + row + 8) * HWL + col;
                *reinterpret_cast<float2*>(o0) =
                    make_float2(acc[mt][nt][0] * RS768, acc[mt][nt][1] * RS768);
                *reinterpret_cast<float2*>(o1) =
                    make_float2(acc[mt][nt][2] * RS768, acc[mt][nt][3] * RS768);
            }
        }
}

extern "C" void kernel_launch(void* const* d_in, const int* in_sizes, int n_in,
                              void* d_out, int out_size) {
    const float* x   = (const float*)d_in[0];   // (16, 256, 56, 56)
    const float* W3  = (const float*)d_in[1];   // (256, 768)
    const float* p7w = (const float*)d_in[2];   // (1, 256, 3, 256)
    float* out = (float*)d_out;                 // (16, 256, 56, 56)

    p_cvtw<<<192, 256>>>((const float4*)W3);
    p_t1  <<<37632, 256>>>(x);
    k2    <<<dim3(2, 6, 48), 256>>>();
    k1    <<<dim3(25, 2, 16), 256>>>();
    p_t6  <<<37632, 256>>>(x);
    k2r   <<<3072, 256>>>((const float4*)p7w);
    k3    <<<dim3(25, 2, 16), 256>>>(out);
}